// round 1
// baseline (speedup 1.0000x reference)
#include <cuda_runtime.h>
#include <cuda_bf16.h>

// Problem: x (8,3,512,512) f32, y (8,3,1024,1024) f32, w1,b1,w2,b2 (3,) f32.
// out_lr = sigmoid(w2 * boxsum(relu(w1*x+b1), dil=2) + b2) * relu(w1*x+b1)
// output = y + nearest_upsample_x2(out_lr)
//
// One fused kernel. Thread handles 2 low-res pixels (w0, w0+1), writes a
// 2x4 high-res patch via two float4 RMWs on y.

#define HH 512
#define WW 512
#define H2 1024
#define W2 1024
#define CC 3

__device__ __forceinline__ float actv(float v, float w1v, float b1v) {
    return fmaxf(fmaf(w1v, v, b1v), 0.0f);
}

__global__ __launch_bounds__(256, 8)
void fused_shift_gate_up_kernel(const float* __restrict__ x,
                                const float* __restrict__ y,
                                const float* __restrict__ w1,
                                const float* __restrict__ b1,
                                const float* __restrict__ w2,
                                const float* __restrict__ b2,
                                float* __restrict__ out)
{
    const int tid   = threadIdx.x;        // 0..255
    const int w0    = tid << 1;           // even low-res column, 0..510
    const int h     = blockIdx.y;         // low-res row 0..511
    const int plane = blockIdx.z;         // b*C + c, 0..23
    const int c     = plane % CC;

    const float w1v = __ldg(w1 + c);
    const float b1v = __ldg(b1 + c);
    const float w2v = __ldg(w2 + c);
    const float b2v = __ldg(b2 + c);

    const float* xp = x + (size_t)plane * (HH * WW);

    float s0 = 0.0f, s1 = 0.0f;   // dilated box sums for pixels w0, w0+1
    float xc0 = 0.0f, xc1 = 0.0f; // relu'd center values

    const bool okL = (w0 >= 2);
    const bool okR = (w0 <= WW - 4);

    #pragma unroll
    for (int dr = 0; dr < 3; ++dr) {
        const int r = h + (dr - 1) * 2;
        if ((unsigned)r < (unsigned)HH) {
            const float* row = xp + (size_t)r * WW;
            float a0 = 0.f, a1 = 0.f, a4 = 0.f, a5 = 0.f;
            if (okL) {
                float2 L = *reinterpret_cast<const float2*>(row + w0 - 2);
                a0 = actv(L.x, w1v, b1v);
                a1 = actv(L.y, w1v, b1v);
            }
            float2 Cv = *reinterpret_cast<const float2*>(row + w0);
            float a2 = actv(Cv.x, w1v, b1v);
            float a3 = actv(Cv.y, w1v, b1v);
            if (okR) {
                float2 R = *reinterpret_cast<const float2*>(row + w0 + 2);
                a4 = actv(R.x, w1v, b1v);
                a5 = actv(R.y, w1v, b1v);
            }
            // pixel w0 taps columns {w0-2, w0, w0+2}; pixel w0+1 taps {w0-1, w0+1, w0+3}
            s0 += a0 + a2 + a4;
            s1 += a1 + a3 + a5;
            if (dr == 1) { xc0 = a2; xc1 = a3; }
        }
    }

    const float g0 = 1.0f / (1.0f + __expf(-fmaf(w2v, s0, b2v)));
    const float g1 = 1.0f / (1.0f + __expf(-fmaf(w2v, s1, b2v)));
    const float o0 = g0 * xc0;
    const float o1 = g1 * xc1;

    // High-res 2x4 patch: rows 2h, 2h+1; cols 2w0 .. 2w0+3 (16B aligned)
    const size_t obase = (size_t)plane * (H2 * W2);
    const size_t r0 = obase + (size_t)(2 * h) * W2 + (size_t)(2 * w0);
    const size_t r1 = r0 + W2;

    float4 y0 = *reinterpret_cast<const float4*>(y + r0);
    float4 y1 = *reinterpret_cast<const float4*>(y + r1);

    float4 u0, u1;
    u0.x = y0.x + o0; u0.y = y0.y + o0; u0.z = y0.z + o1; u0.w = y0.w + o1;
    u1.x = y1.x + o0; u1.y = y1.y + o0; u1.z = y1.z + o1; u1.w = y1.w + o1;

    *reinterpret_cast<float4*>(out + r0) = u0;
    *reinterpret_cast<float4*>(out + r1) = u1;
}

extern "C" void kernel_launch(void* const* d_in, const int* in_sizes, int n_in,
                              void* d_out, int out_size)
{
    const float* x  = (const float*)d_in[0];
    const float* y  = (const float*)d_in[1];
    const float* w1 = (const float*)d_in[2];
    const float* b1 = (const float*)d_in[3];
    const float* w2 = (const float*)d_in[4];
    const float* b2 = (const float*)d_in[5];
    float* out = (float*)d_out;

    dim3 grid(1, HH, 8 * CC);   // one block per low-res row per plane
    dim3 block(256, 1, 1);      // 256 threads x 2 low-res pixels = 512 cols
    fused_shift_gate_up_kernel<<<grid, block>>>(x, y, w1, b1, w2, b2, out);
}

// round 2
// speedup vs baseline: 1.1097x; 1.1097x over previous
#include <cuda_runtime.h>
#include <cuda_bf16.h>

// x (8,3,512,512) f32, y (8,3,1024,1024) f32, w1,b1,w2,b2 (3,) f32.
// out_lr = sigmoid(w2 * boxsum3x3_dil2(relu(w1*x+b1)) + b2) * relu(w1*x+b1)
// output = y + nearest_upsample_x2(out_lr)
//
// One fused kernel. Thread handles 4 low-res pixels -> 2x8 high-res patch.
// x loads: 3 aligned float4 per row x 3 rows. y/out: 4 float4 loads + 4 stores
// with streaming hints (x stays resident in L2; y/out bypass-evict-first).

#define HH 512
#define WW 512
#define H2 1024
#define W2 1024
#define CC 3

__device__ __forceinline__ float actv(float v, float w1v, float b1v) {
    return fmaxf(fmaf(w1v, v, b1v), 0.0f);
}

__global__ __launch_bounds__(128, 12)
void fused_shift_gate_up_kernel(const float* __restrict__ x,
                                const float* __restrict__ y,
                                const float* __restrict__ w1,
                                const float* __restrict__ b1,
                                const float* __restrict__ w2,
                                const float* __restrict__ b2,
                                float* __restrict__ out)
{
    const int tid   = threadIdx.x;        // 0..127
    const int w0    = tid << 2;           // low-res column base, mult of 4
    const int h     = blockIdx.y;         // low-res row
    const int plane = blockIdx.z;         // b*C + c
    const int c     = plane % CC;

    const float w1v = __ldg(w1 + c);
    const float b1v = __ldg(b1 + c);
    const float w2v = __ldg(w2 + c);
    const float b2v = __ldg(b2 + c);

    const float* xp = x + (size_t)plane * (HH * WW);

    // box sums for pixels w0..w0+3
    float s0 = 0.f, s1 = 0.f, s2 = 0.f, s3 = 0.f;
    // relu'd center values
    float xc0 = 0.f, xc1 = 0.f, xc2 = 0.f, xc3 = 0.f;

    const bool okL = (w0 >= 4);          // need cols w0-2, w0-1
    const bool okR = (w0 <= WW - 8);     // need cols w0+4, w0+5

    #pragma unroll
    for (int dr = 0; dr < 3; ++dr) {
        const int r = h + (dr - 1) * 2;
        if ((unsigned)r < (unsigned)HH) {
            const float* row = xp + (size_t)r * WW;
            float aL2 = 0.f, aL1 = 0.f, aR0 = 0.f, aR1 = 0.f;
            if (okL) {
                float4 L = *reinterpret_cast<const float4*>(row + w0 - 4);
                aL2 = actv(L.z, w1v, b1v);
                aL1 = actv(L.w, w1v, b1v);
            }
            float4 Cv = *reinterpret_cast<const float4*>(row + w0);
            float aC0 = actv(Cv.x, w1v, b1v);
            float aC1 = actv(Cv.y, w1v, b1v);
            float aC2 = actv(Cv.z, w1v, b1v);
            float aC3 = actv(Cv.w, w1v, b1v);
            if (okR) {
                float4 R = *reinterpret_cast<const float4*>(row + w0 + 4);
                aR0 = actv(R.x, w1v, b1v);
                aR1 = actv(R.y, w1v, b1v);
            }
            const float t02 = aC0 + aC2;
            const float t13 = aC1 + aC3;
            s0 += aL2 + t02;
            s1 += aL1 + t13;
            s2 += t02 + aR0;
            s3 += t13 + aR1;
            if (dr == 1) { xc0 = aC0; xc1 = aC1; xc2 = aC2; xc3 = aC3; }
        }
    }

    const float o0 = xc0 / (1.0f + __expf(-fmaf(w2v, s0, b2v)));
    const float o1 = xc1 / (1.0f + __expf(-fmaf(w2v, s1, b2v)));
    const float o2 = xc2 / (1.0f + __expf(-fmaf(w2v, s2, b2v)));
    const float o3 = xc3 / (1.0f + __expf(-fmaf(w2v, s3, b2v)));

    // High-res 2x8 patch: rows 2h, 2h+1; cols 2*w0 .. 2*w0+7 (16B aligned)
    const size_t obase = (size_t)plane * ((size_t)H2 * W2);
    const size_t r0 = obase + (size_t)(2 * h) * W2 + (size_t)(2 * w0);
    const size_t r1 = r0 + W2;

    float4 ya0 = __ldcs(reinterpret_cast<const float4*>(y + r0));
    float4 yb0 = __ldcs(reinterpret_cast<const float4*>(y + r0 + 4));
    float4 ya1 = __ldcs(reinterpret_cast<const float4*>(y + r1));
    float4 yb1 = __ldcs(reinterpret_cast<const float4*>(y + r1 + 4));

    float4 ua0 = make_float4(ya0.x + o0, ya0.y + o0, ya0.z + o1, ya0.w + o1);
    float4 ub0 = make_float4(yb0.x + o2, yb0.y + o2, yb0.z + o3, yb0.w + o3);
    float4 ua1 = make_float4(ya1.x + o0, ya1.y + o0, ya1.z + o1, ya1.w + o1);
    float4 ub1 = make_float4(yb1.x + o2, yb1.y + o2, yb1.z + o3, yb1.w + o3);

    __stcs(reinterpret_cast<float4*>(out + r0),     ua0);
    __stcs(reinterpret_cast<float4*>(out + r0 + 4), ub0);
    __stcs(reinterpret_cast<float4*>(out + r1),     ua1);
    __stcs(reinterpret_cast<float4*>(out + r1 + 4), ub1);
}

extern "C" void kernel_launch(void* const* d_in, const int* in_sizes, int n_in,
                              void* d_out, int out_size)
{
    const float* x  = (const float*)d_in[0];
    const float* y  = (const float*)d_in[1];
    const float* w1 = (const float*)d_in[2];
    const float* b1 = (const float*)d_in[3];
    const float* w2 = (const float*)d_in[4];
    const float* b2 = (const float*)d_in[5];
    float* out = (float*)d_out;

    dim3 grid(1, HH, 8 * CC);   // one block per low-res row per plane
    dim3 block(128, 1, 1);      // 128 threads x 4 low-res pixels = 512 cols
    fused_shift_gate_up_kernel<<<grid, block>>>(x, y, w1, b1, w2, b2, out);
}